// round 4
// baseline (speedup 1.0000x reference)
#include <cuda_runtime.h>
#include <cstddef>

// Problem constants (fixed by the reference)
#define N_NODES 50000
#define N_EDGES 312500
#define D_FEAT  256          // D_IN == D_HID == 256
#define D_OUT   128
#define KCHEB   3
#define KTOT    (KCHEB * D_FEAT)   // 768

// ---------------- scratch (static device globals; no allocation) ----------------
__device__ __align__(16) float g_tx1[(size_t)N_NODES * D_FEAT];
__device__ __align__(16) float g_tx2[(size_t)N_NODES * D_FEAT];
__device__ __align__(16) float g_h  [(size_t)N_NODES * D_FEAT];
__device__ float g_deg[N_NODES];
__device__ int   g_cnt[N_NODES];
__device__ int   g_fill[N_NODES];
__device__ int   g_rowptr[N_NODES + 1];
__device__ int   g_dst[N_EDGES];
__device__ float g_w[N_EDGES];
__device__ int   g_is64;   // 1 if edge_index is actually int64 on device

// Device-side scratch-buffer selection: 0 = external pointer, 1/2/3 = globals.
template <int ID>
__device__ __forceinline__ float* sel_buf(float* ext) {
    if (ID == 1) return g_tx1;
    if (ID == 2) return g_tx2;
    if (ID == 3) return g_h;
    return ext;
}
template <int ID>
__device__ __forceinline__ const float* sel_cbuf(const float* ext) {
    if (ID == 1) return g_tx1;
    if (ID == 2) return g_tx2;
    if (ID == 3) return g_h;
    return ext;
}

// Edge-index accessors robust to int32 vs int64 storage.
// int32 layout: ids at [i].  int64 layout: low word of value i at [2*i] (LE).
__device__ __forceinline__ int edge_row(const int* ei, int e) {
    return g_is64 ? ei[2 * e] : ei[e];
}
__device__ __forceinline__ int edge_col(const int* ei, int e) {
    return g_is64 ? ei[2 * (N_EDGES + e)] : ei[N_EDGES + e];
}

// ---------------- dtype detection ----------------
// If the buffer holds int64 node ids (< 50000), every high 32-bit word of the
// first values is 0. For int32 data those words are real ids, uniformly random
// in [0, 50000) -> P(2048 consecutive being zero) ~ 0.
__global__ void detect_kernel(const int* __restrict__ ei) {
    __shared__ int any_nonzero;
    if (threadIdx.x == 0) any_nonzero = 0;
    __syncthreads();
    for (int i = threadIdx.x; i < 2048; i += blockDim.x) {
        if (ei[2 * i + 1] != 0) { any_nonzero = 1; break; }
    }
    __syncthreads();
    if (threadIdx.x == 0) g_is64 = (any_nonzero == 0) ? 1 : 0;
}

// ---------------- CSR build kernels ----------------

__global__ void zero_kernel() {
    int i = blockIdx.x * blockDim.x + threadIdx.x;
    if (i < N_NODES) {
        g_deg[i] = 0.f;
        g_cnt[i] = 0;
        g_fill[i] = 0;
    }
}

__global__ void deg_count_kernel(const int* __restrict__ ei,
                                 const float* __restrict__ ew) {
    int e = blockIdx.x * blockDim.x + threadIdx.x;
    if (e >= N_EDGES) return;
    int r = edge_row(ei, e);
    atomicAdd(&g_deg[r], ew[e]);
    atomicAdd(&g_cnt[r], 1);
}

// single-block exclusive scan of g_cnt -> g_rowptr
__global__ void scan_kernel() {
    const int T = 1024;
    int t = threadIdx.x;
    int per = (N_NODES + T - 1) / T;  // 49
    int start = t * per;
    int end = start + per; if (end > N_NODES) end = N_NODES;
    if (start > N_NODES) start = N_NODES;

    int local = 0;
    for (int i = start; i < end; i++) local += g_cnt[i];

    __shared__ int sums[1024];
    sums[t] = local;
    __syncthreads();
    // Hillis-Steele inclusive scan
    for (int off = 1; off < T; off <<= 1) {
        int v = (t >= off) ? sums[t - off] : 0;
        __syncthreads();
        sums[t] += v;
        __syncthreads();
    }
    int run = sums[t] - local;  // exclusive prefix for this thread's segment
    for (int i = start; i < end; i++) {
        g_rowptr[i] = run;
        run += g_cnt[i];
    }
    if (t == 0) g_rowptr[N_NODES] = sums[T - 1];
}

__global__ void build_kernel(const int* __restrict__ ei,
                             const float* __restrict__ ew) {
    int e = blockIdx.x * blockDim.x + threadIdx.x;
    if (e >= N_EDGES) return;
    int r = edge_row(ei, e);
    int c = edge_col(ei, e);
    float dr = g_deg[r], dc = g_deg[c];
    float ir = dr > 0.f ? rsqrtf(dr) : 0.f;
    float ic = dc > 0.f ? rsqrtf(dc) : 0.f;
    float w = -ir * ew[e] * ic;
    int pos = atomicAdd(&g_fill[r], 1);
    int idx = g_rowptr[r] + pos;
    g_dst[idx] = c;
    g_w[idx] = w;
}

// ---------------- SpMM ----------------
// dst[row] = alpha * sum_e w_e * src[dst_e]  + beta * sub[row]
// one warp per row; D=256 -> 2x float4 per lane
// SRC/SUB/DST are buffer IDs (0 = use external pointer, -1 for SUB = none).
template <int SRC, int SUB, int DST>
__global__ void spmm_kernel(const float* __restrict__ ext_src,
                            const float* __restrict__ ext_sub,
                            float alpha, float beta) {
    const float* src = sel_cbuf<SRC>(ext_src);
    float*       dst = sel_buf<DST>(nullptr);

    int warp = (blockIdx.x * blockDim.x + threadIdx.x) >> 5;
    int lane = threadIdx.x & 31;
    if (warp >= N_NODES) return;
    int s = g_rowptr[warp];
    int e = g_rowptr[warp + 1];
    float4 a0 = make_float4(0.f, 0.f, 0.f, 0.f);
    float4 a1 = make_float4(0.f, 0.f, 0.f, 0.f);
    for (int i = s; i < e; i++) {
        float w = g_w[i];
        const float4* hp = (const float4*)(src + (size_t)g_dst[i] * D_FEAT);
        float4 v0 = hp[lane];
        float4 v1 = hp[lane + 32];
        a0.x += w * v0.x; a0.y += w * v0.y; a0.z += w * v0.z; a0.w += w * v0.w;
        a1.x += w * v1.x; a1.y += w * v1.y; a1.z += w * v1.z; a1.w += w * v1.w;
    }
    float4* op = (float4*)(dst + (size_t)warp * D_FEAT);
    if (SUB >= 0) {
        const float* sub = sel_cbuf<(SUB >= 0 ? SUB : 0)>(ext_sub);
        const float4* sp = (const float4*)(sub + (size_t)warp * D_FEAT);
        float4 s0 = sp[lane];
        float4 s1 = sp[lane + 32];
        a0.x = alpha * a0.x + beta * s0.x; a0.y = alpha * a0.y + beta * s0.y;
        a0.z = alpha * a0.z + beta * s0.z; a0.w = alpha * a0.w + beta * s0.w;
        a1.x = alpha * a1.x + beta * s1.x; a1.y = alpha * a1.y + beta * s1.y;
        a1.z = alpha * a1.z + beta * s1.z; a1.w = alpha * a1.w + beta * s1.w;
    }
    op[lane] = a0;
    op[lane + 32] = a1;
}

// ---------------- fused 3-term GEMM ----------------
// C[M,N] = relu?( [A0|A1|A2] (M x 768) @ B (768 x N) + bias )
// A1 = g_tx1, A2 = g_tx2 always. A0 and C selected by template ID.
// BM=BN=128, BK=8, 256 threads, 8x8 per thread
#define BM 128
#define BN 128
#define BK 8
template <int A0ID, int CID, int NN, int RELU>
__global__ __launch_bounds__(256, 2)
void gemm3_kernel(const float* __restrict__ ext_a0,
                  const float* __restrict__ B,
                  const float* __restrict__ bias,
                  float* __restrict__ ext_c) {
    const float* A0 = sel_cbuf<A0ID>(ext_a0);
    const float* A1 = g_tx1;
    const float* A2 = g_tx2;
    float*       C  = sel_buf<CID>(ext_c);
    const int M = N_NODES;
    const int N = NN;

    __shared__ __align__(16) float As[BK][BM];
    __shared__ __align__(16) float Bs[BK][BN];

    int t = threadIdx.x;
    int bm = blockIdx.y * BM;
    int bn = blockIdx.x * BN;

    int tm = (t >> 4) << 3;   // 0..120
    int tn = (t & 15) << 3;   // 0..120

    int a_row = t >> 1;          // 0..127
    int a_k4  = (t & 1) * 4;     // 0 or 4
    int b_k   = t >> 5;          // 0..7
    int b_c   = (t & 31) * 4;    // 0..124

    float acc[8][8];
#pragma unroll
    for (int i = 0; i < 8; i++)
#pragma unroll
        for (int j = 0; j < 8; j++) acc[i][j] = 0.f;

    for (int k0 = 0; k0 < KTOT; k0 += BK) {
        // A tile (transposed into As[k][m])
        {
            int m = bm + a_row;
            int gk = k0 + a_k4;
            float4 v = make_float4(0.f, 0.f, 0.f, 0.f);
            if (m < M) {
                const float* Ab = (gk < 256) ? A0 : ((gk < 512) ? A1 : A2);
                v = *(const float4*)(Ab + (size_t)m * D_FEAT + (gk & 255));
            }
            As[a_k4 + 0][a_row] = v.x;
            As[a_k4 + 1][a_row] = v.y;
            As[a_k4 + 2][a_row] = v.z;
            As[a_k4 + 3][a_row] = v.w;
        }
        // B tile
        {
            float4 v = *(const float4*)(B + (size_t)(k0 + b_k) * N + bn + b_c);
            *(float4*)&Bs[b_k][b_c] = v;
        }
        __syncthreads();
#pragma unroll
        for (int kk = 0; kk < BK; kk++) {
            float ra[8], rb[8];
            *(float4*)&ra[0] = *(const float4*)&As[kk][tm];
            *(float4*)&ra[4] = *(const float4*)&As[kk][tm + 4];
            *(float4*)&rb[0] = *(const float4*)&Bs[kk][tn];
            *(float4*)&rb[4] = *(const float4*)&Bs[kk][tn + 4];
#pragma unroll
            for (int i = 0; i < 8; i++)
#pragma unroll
                for (int j = 0; j < 8; j++)
                    acc[i][j] += ra[i] * rb[j];
        }
        __syncthreads();
    }

    // epilogue
#pragma unroll
    for (int i = 0; i < 8; i++) {
        int m = bm + tm + i;
        if (m >= M) continue;
#pragma unroll
        for (int j = 0; j < 8; j += 4) {
            float4 o;
            o.x = acc[i][j + 0] + bias[bn + tn + j + 0];
            o.y = acc[i][j + 1] + bias[bn + tn + j + 1];
            o.z = acc[i][j + 2] + bias[bn + tn + j + 2];
            o.w = acc[i][j + 3] + bias[bn + tn + j + 3];
            if (RELU) {
                o.x = fmaxf(o.x, 0.f); o.y = fmaxf(o.y, 0.f);
                o.z = fmaxf(o.z, 0.f); o.w = fmaxf(o.w, 0.f);
            }
            *(float4*)(C + (size_t)m * N + bn + tn + j) = o;
        }
    }
}

// ---------------- launch ----------------

extern "C" void kernel_launch(void* const* d_in, const int* in_sizes, int n_in,
                              void* d_out, int out_size) {
    const float* x  = (const float*)d_in[0];
    const int*   ei = (const int*)d_in[1];     // int32 (or int64 low-words; detected)
    const float* ew = (const float*)d_in[2];
    const float* W1 = (const float*)d_in[3];   // [3,256,256] == [768,256]
    const float* b1 = (const float*)d_in[4];
    const float* W2 = (const float*)d_in[5];   // [3,256,128] == [768,128]
    const float* b2 = (const float*)d_in[6];
    float*       out = (float*)d_out;

    // 0. dtype sniff + CSR build
    detect_kernel<<<1, 256>>>(ei);
    zero_kernel<<<(N_NODES + 255) / 256, 256>>>();
    deg_count_kernel<<<(N_EDGES + 255) / 256, 256>>>(ei, ew);
    scan_kernel<<<1, 1024>>>();
    build_kernel<<<(N_EDGES + 255) / 256, 256>>>(ei, ew);

    const int spmm_blocks = (N_NODES * 32 + 255) / 256;

    // ---- layer 1 ----
    // tx1 = L_hat @ x
    spmm_kernel<0, -1, 1><<<spmm_blocks, 256>>>(x, nullptr, 1.f, 0.f);
    // tx2 = 2 * (L_hat @ tx1) - x
    spmm_kernel<1, 0, 2><<<spmm_blocks, 256>>>(nullptr, x, 2.f, -1.f);
    // h = relu([x|tx1|tx2] @ W1 + b1)
    {
        dim3 grid(D_FEAT / BN, (N_NODES + BM - 1) / BM);
        gemm3_kernel<0, 3, D_FEAT, 1><<<grid, 256>>>(x, W1, b1, nullptr);
    }

    // ---- layer 2 ----
    // tx1 = L_hat @ h
    spmm_kernel<3, -1, 1><<<spmm_blocks, 256>>>(nullptr, nullptr, 1.f, 0.f);
    // tx2 = 2 * (L_hat @ tx1) - h
    spmm_kernel<1, 3, 2><<<spmm_blocks, 256>>>(nullptr, nullptr, 2.f, -1.f);
    // out = [h|tx1|tx2] @ W2 + b2
    {
        dim3 grid(D_OUT / BN, (N_NODES + BM - 1) / BM);
        gemm3_kernel<3, 0, D_OUT, 0><<<grid, 256>>>(nullptr, W2, b2, out);
    }

    (void)in_sizes; (void)n_in; (void)out_size;
}

// round 5
// speedup vs baseline: 2.0018x; 2.0018x over previous
#include <cuda_runtime.h>
#include <cstdint>
#include <cstddef>

// Problem constants (fixed by the reference)
#define N_NODES 50000
#define N_EDGES 312500
#define D_FEAT  256          // D_IN == D_HID == 256
#define D_OUT   128
#define KTOT    768          // 3 * 256

// ---------------- scratch (static device globals; no allocation) ----------------
__device__ __align__(16) float g_tx1[(size_t)N_NODES * D_FEAT];
__device__ __align__(16) float g_tx2[(size_t)N_NODES * D_FEAT];
__device__ __align__(16) float g_h  [(size_t)N_NODES * D_FEAT];
__device__ float g_deg[N_NODES];
__device__ int   g_cnt[N_NODES];
__device__ int   g_fill[N_NODES];
__device__ int   g_rowptr[N_NODES + 1];
__device__ int   g_dst[N_EDGES];
__device__ float g_w[N_EDGES];
__device__ int   g_is64;        // 1 if edge_index is actually int64 on device
__device__ int   g_bsum[256];   // per-block sums for decomposed scan
__device__ int   g_boff[256];   // exclusive block offsets

#define SCAN_BLOCKS 196         // 196 * 256 = 50176 >= N_NODES

// Device-side scratch-buffer selection: 0 = external pointer, 1/2/3 = globals.
template <int ID>
__device__ __forceinline__ float* sel_buf(float* ext) {
    if (ID == 1) return g_tx1;
    if (ID == 2) return g_tx2;
    if (ID == 3) return g_h;
    return ext;
}
template <int ID>
__device__ __forceinline__ const float* sel_cbuf(const float* ext) {
    if (ID == 1) return g_tx1;
    if (ID == 2) return g_tx2;
    if (ID == 3) return g_h;
    return ext;
}

// Edge-index accessors robust to int32 vs int64 storage.
__device__ __forceinline__ int edge_row(const int* ei, int e) {
    return g_is64 ? ei[2 * e] : ei[e];
}
__device__ __forceinline__ int edge_col(const int* ei, int e) {
    return g_is64 ? ei[2 * (N_EDGES + e)] : ei[N_EDGES + e];
}

// ---------------- dtype detection ----------------
__global__ void detect_kernel(const int* __restrict__ ei) {
    __shared__ int any_nonzero;
    if (threadIdx.x == 0) any_nonzero = 0;
    __syncthreads();
    for (int i = threadIdx.x; i < 2048; i += blockDim.x) {
        if (ei[2 * i + 1] != 0) { any_nonzero = 1; break; }
    }
    __syncthreads();
    if (threadIdx.x == 0) g_is64 = (any_nonzero == 0) ? 1 : 0;
}

// ---------------- CSR build ----------------

__global__ void zero_kernel() {
    int i = blockIdx.x * blockDim.x + threadIdx.x;
    if (i < N_NODES) {
        g_deg[i] = 0.f;
        g_cnt[i] = 0;
        g_fill[i] = 0;
    }
}

__global__ void deg_count_kernel(const int* __restrict__ ei,
                                 const float* __restrict__ ew) {
    int e = blockIdx.x * blockDim.x + threadIdx.x;
    if (e >= N_EDGES) return;
    int r = edge_row(ei, e);
    atomicAdd(&g_deg[r], ew[e]);
    atomicAdd(&g_cnt[r], 1);
}

// Decomposed scan: (1) per-block sums, (2) scan of block sums, (3) local scans.
__global__ void scan_pre_kernel() {
    __shared__ int red[256];
    int t = threadIdx.x;
    int i = blockIdx.x * 256 + t;
    red[t] = (i < N_NODES) ? g_cnt[i] : 0;
    __syncthreads();
    for (int off = 128; off > 0; off >>= 1) {
        if (t < off) red[t] += red[t + off];
        __syncthreads();
    }
    if (t == 0) g_bsum[blockIdx.x] = red[0];
}

__global__ void scan_mid_kernel() {
    __shared__ int s[256];
    int t = threadIdx.x;
    int v = (t < SCAN_BLOCKS) ? g_bsum[t] : 0;
    s[t] = v;
    __syncthreads();
    for (int off = 1; off < 256; off <<= 1) {
        int u = (t >= off) ? s[t - off] : 0;
        __syncthreads();
        s[t] += u;
        __syncthreads();
    }
    if (t < SCAN_BLOCKS) g_boff[t] = s[t] - v;   // exclusive
    if (t == 255) g_rowptr[N_NODES] = s[255];    // total (== N_EDGES)
}

__global__ void scan_post_kernel() {
    __shared__ int s[256];
    int t = threadIdx.x;
    int i = blockIdx.x * 256 + t;
    int v = (i < N_NODES) ? g_cnt[i] : 0;
    s[t] = v;
    __syncthreads();
    for (int off = 1; off < 256; off <<= 1) {
        int u = (t >= off) ? s[t - off] : 0;
        __syncthreads();
        s[t] += u;
        __syncthreads();
    }
    if (i < N_NODES) g_rowptr[i] = g_boff[blockIdx.x] + s[t] - v;  // exclusive
}

__global__ void build_kernel(const int* __restrict__ ei,
                             const float* __restrict__ ew) {
    int e = blockIdx.x * blockDim.x + threadIdx.x;
    if (e >= N_EDGES) return;
    int r = edge_row(ei, e);
    int c = edge_col(ei, e);
    float dr = g_deg[r], dc = g_deg[c];
    float ir = dr > 0.f ? rsqrtf(dr) : 0.f;
    float ic = dc > 0.f ? rsqrtf(dc) : 0.f;
    float w = -ir * ew[e] * ic;
    int pos = atomicAdd(&g_fill[r], 1);
    int idx = g_rowptr[r] + pos;
    g_dst[idx] = c;
    g_w[idx] = w;
}

// ---------------- SpMM (unchanged from the passing R4 kernel) ----------------
template <int SRC, int SUB, int DST>
__global__ void spmm_kernel(const float* __restrict__ ext_src,
                            const float* __restrict__ ext_sub,
                            float alpha, float beta) {
    const float* src = sel_cbuf<SRC>(ext_src);
    float*       dst = sel_buf<DST>(nullptr);

    int warp = (blockIdx.x * blockDim.x + threadIdx.x) >> 5;
    int lane = threadIdx.x & 31;
    if (warp >= N_NODES) return;
    int s = g_rowptr[warp];
    int e = g_rowptr[warp + 1];
    float4 a0 = make_float4(0.f, 0.f, 0.f, 0.f);
    float4 a1 = make_float4(0.f, 0.f, 0.f, 0.f);
    for (int i = s; i < e; i++) {
        float w = g_w[i];
        const float4* hp = (const float4*)(src + (size_t)g_dst[i] * D_FEAT);
        float4 v0 = hp[lane];
        float4 v1 = hp[lane + 32];
        a0.x += w * v0.x; a0.y += w * v0.y; a0.z += w * v0.z; a0.w += w * v0.w;
        a1.x += w * v1.x; a1.y += w * v1.y; a1.z += w * v1.z; a1.w += w * v1.w;
    }
    float4* op = (float4*)(dst + (size_t)warp * D_FEAT);
    if (SUB >= 0) {
        const float* sub = sel_cbuf<(SUB >= 0 ? SUB : 0)>(ext_sub);
        const float4* sp = (const float4*)(sub + (size_t)warp * D_FEAT);
        float4 s0 = sp[lane];
        float4 s1 = sp[lane + 32];
        a0.x = alpha * a0.x + beta * s0.x; a0.y = alpha * a0.y + beta * s0.y;
        a0.z = alpha * a0.z + beta * s0.z; a0.w = alpha * a0.w + beta * s0.w;
        a1.x = alpha * a1.x + beta * s1.x; a1.y = alpha * a1.y + beta * s1.y;
        a1.z = alpha * a1.z + beta * s1.z; a1.w = alpha * a1.w + beta * s1.w;
    }
    op[lane] = a0;
    op[lane + 32] = a1;
}

// ---------------- tf32 tensor-core fused 3-term GEMM ----------------
// C[M,N] = relu?( [A0|tx1|tx2] (M x 768) @ B (768 x N) + bias )
// Block 128x128, 4 warps of 64x64, mma.sync.m16n8k8.tf32, BK=32.

__device__ __forceinline__ uint32_t f2tf32(float x) {
    uint32_t r;
    asm("cvt.rna.tf32.f32 %0, %1;" : "=r"(r) : "f"(x));
    return r;
}

__device__ __forceinline__ void mma_tf32(float c[4], const uint32_t a[4],
                                         const uint32_t b[2]) {
    asm volatile(
        "mma.sync.aligned.m16n8k8.row.col.f32.tf32.tf32.f32 "
        "{%0,%1,%2,%3}, {%4,%5,%6,%7}, {%8,%9}, {%0,%1,%2,%3};\n"
        : "+f"(c[0]), "+f"(c[1]), "+f"(c[2]), "+f"(c[3])
        : "r"(a[0]), "r"(a[1]), "r"(a[2]), "r"(a[3]), "r"(b[0]), "r"(b[1]));
}

template <int A0ID, int CID, int NN, int RELU>
__global__ __launch_bounds__(128, 2)
void gemm3_tc(const float* __restrict__ ext_a0,
              const float* __restrict__ B,
              const float* __restrict__ bias,
              float* __restrict__ ext_c) {
    const float* A0 = sel_cbuf<A0ID>(ext_a0);
    float*       C  = sel_buf<CID>(ext_c);
    const int M = N_NODES;

    // Padded for conflict-free fragment loads:
    //  A frag addr = 36*m + k   -> bank (4g+t)%32 across warp: distinct
    //  B frag addr = 132*k + n  -> bank (4t+g)%32 across warp: distinct
    __shared__ __align__(16) float As[128][36];   // [m][k] tf32 bits
    __shared__ __align__(16) float Bs[32][132];   // [k][n] tf32 bits

    const int tid  = threadIdx.x;
    const int lane = tid & 31;
    const int wid  = tid >> 5;
    const int g = lane >> 2;    // 0..7
    const int t = lane & 3;     // 0..3

    const int bm = blockIdx.y * 128;
    const int bn = blockIdx.x * 128;
    const int wm = (wid & 1) * 64;   // warp tile origin (m)
    const int wn = (wid >> 1) * 64;  // warp tile origin (n)

    float acc[4][8][4];
#pragma unroll
    for (int i = 0; i < 4; i++)
#pragma unroll
        for (int j = 0; j < 8; j++)
#pragma unroll
            for (int q = 0; q < 4; q++) acc[i][j][q] = 0.f;

    const int m_ld = bm + tid;          // the A row this thread stages
    const bool mv = (m_ld < M);
    const int bk_row = tid >> 5;        // 0..3   (B stage k base)
    const int bn4    = (lane) * 4;      // 0..124 (B stage n offset)

    for (int s = 0; s < KTOT / 32; s++) {
        // ---- stage A: row m_ld, k = s*32 .. +31 (one 256-chunk per buffer) ----
        {
            const float* Ab = (s < 8) ? A0 : ((s < 16) ? g_tx1 : g_tx2);
            const int kbase = (s * 32) & 255;
#pragma unroll
            for (int c4 = 0; c4 < 8; c4++) {
                float4 v = mv ? *(const float4*)(Ab + (size_t)m_ld * D_FEAT + kbase + c4 * 4)
                              : make_float4(0.f, 0.f, 0.f, 0.f);
                float4 cv;
                cv.x = __uint_as_float(f2tf32(v.x));
                cv.y = __uint_as_float(f2tf32(v.y));
                cv.z = __uint_as_float(f2tf32(v.z));
                cv.w = __uint_as_float(f2tf32(v.w));
                *(float4*)&As[tid][c4 * 4] = cv;
            }
        }
        // ---- stage B: [32][128] tile of W ----
        {
#pragma unroll
            for (int r = 0; r < 8; r++) {
                int k = r * 4 + bk_row;
                float4 v = *(const float4*)(B + (size_t)(s * 32 + k) * NN + bn + bn4);
                float4 cv;
                cv.x = __uint_as_float(f2tf32(v.x));
                cv.y = __uint_as_float(f2tf32(v.y));
                cv.z = __uint_as_float(f2tf32(v.z));
                cv.w = __uint_as_float(f2tf32(v.w));
                *(float4*)&Bs[k][bn4] = cv;
            }
        }
        __syncthreads();

        // ---- compute: 4 k-steps of 8 ----
#pragma unroll
        for (int ks = 0; ks < 4; ks++) {
            const int k0 = ks * 8;
            uint32_t afr[4][4];
            uint32_t bfr[8][2];
#pragma unroll
            for (int i = 0; i < 4; i++) {
                int r0 = wm + 16 * i + g;
                afr[i][0] = __float_as_uint(As[r0][k0 + t]);
                afr[i][1] = __float_as_uint(As[r0 + 8][k0 + t]);
                afr[i][2] = __float_as_uint(As[r0][k0 + t + 4]);
                afr[i][3] = __float_as_uint(As[r0 + 8][k0 + t + 4]);
            }
#pragma unroll
            for (int j = 0; j < 8; j++) {
                bfr[j][0] = __float_as_uint(Bs[k0 + t][wn + 8 * j + g]);
                bfr[j][1] = __float_as_uint(Bs[k0 + t + 4][wn + 8 * j + g]);
            }
#pragma unroll
            for (int i = 0; i < 4; i++)
#pragma unroll
                for (int j = 0; j < 8; j++)
                    mma_tf32(acc[i][j], afr[i], bfr[j]);
        }
        __syncthreads();
    }

    // ---- epilogue: bias (+ReLU), float2 stores ----
#pragma unroll
    for (int i = 0; i < 4; i++) {
        int r0 = bm + wm + 16 * i + g;
        int r1 = r0 + 8;
#pragma unroll
        for (int j = 0; j < 8; j++) {
            int col = bn + wn + 8 * j + 2 * t;
            float bb0 = bias[col], bb1 = bias[col + 1];
            float v0 = acc[i][j][0] + bb0, v1 = acc[i][j][1] + bb1;
            float v2 = acc[i][j][2] + bb0, v3 = acc[i][j][3] + bb1;
            if (RELU) {
                v0 = fmaxf(v0, 0.f); v1 = fmaxf(v1, 0.f);
                v2 = fmaxf(v2, 0.f); v3 = fmaxf(v3, 0.f);
            }
            if (r0 < M) *(float2*)(C + (size_t)r0 * NN + col) = make_float2(v0, v1);
            if (r1 < M) *(float2*)(C + (size_t)r1 * NN + col) = make_float2(v2, v3);
        }
    }
}

// ---------------- launch ----------------

extern "C" void kernel_launch(void* const* d_in, const int* in_sizes, int n_in,
                              void* d_out, int out_size) {
    const float* x  = (const float*)d_in[0];
    const int*   ei = (const int*)d_in[1];     // int32 (int64 low-words detected)
    const float* ew = (const float*)d_in[2];
    const float* W1 = (const float*)d_in[3];   // [3,256,256] == [768,256]
    const float* b1 = (const float*)d_in[4];
    const float* W2 = (const float*)d_in[5];   // [3,256,128] == [768,128]
    const float* b2 = (const float*)d_in[6];
    float*       out = (float*)d_out;

    // 0. dtype sniff + CSR build (decomposed scan)
    detect_kernel<<<1, 256>>>(ei);
    zero_kernel<<<(N_NODES + 255) / 256, 256>>>();
    deg_count_kernel<<<(N_EDGES + 255) / 256, 256>>>(ei, ew);
    scan_pre_kernel<<<SCAN_BLOCKS, 256>>>();
    scan_mid_kernel<<<1, 256>>>();
    scan_post_kernel<<<SCAN_BLOCKS, 256>>>();
    build_kernel<<<(N_EDGES + 255) / 256, 256>>>(ei, ew);

    const int spmm_blocks = (N_NODES * 32 + 255) / 256;

    // ---- layer 1 ----
    spmm_kernel<0, -1, 1><<<spmm_blocks, 256>>>(x, nullptr, 1.f, 0.f);
    spmm_kernel<1, 0, 2><<<spmm_blocks, 256>>>(nullptr, x, 2.f, -1.f);
    {
        dim3 grid(D_FEAT / 128, (N_NODES + 127) / 128);
        gemm3_tc<0, 3, D_FEAT, 1><<<grid, 128>>>(x, W1, b1, nullptr);
    }

    // ---- layer 2 ----
    spmm_kernel<3, -1, 1><<<spmm_blocks, 256>>>(nullptr, nullptr, 1.f, 0.f);
    spmm_kernel<1, 3, 2><<<spmm_blocks, 256>>>(nullptr, nullptr, 2.f, -1.f);
    {
        dim3 grid(D_OUT / 128, (N_NODES + 127) / 128);
        gemm3_tc<3, 0, D_OUT, 0><<<grid, 128>>>(nullptr, W2, b2, out);
    }

    (void)in_sizes; (void)n_in; (void)out_size;
}

// round 6
// speedup vs baseline: 2.5731x; 1.2854x over previous
#include <cuda_runtime.h>
#include <cstdint>
#include <cstddef>

// Problem constants (fixed by the reference)
#define N_NODES 50000
#define N_EDGES 312500
#define D_FEAT  256
#define D_OUT   128

#define SCAN_BLOCKS 196         // 196 * 256 = 50176 >= N_NODES

// ---------------- scratch (static device globals; no allocation) ----------------
__device__ __align__(16) float g_tx1[(size_t)N_NODES * D_FEAT];
__device__ __align__(16) float g_tx2[(size_t)N_NODES * D_FEAT];
__device__ __align__(16) float g_h  [(size_t)N_NODES * D_FEAT];
__device__ __align__(16) float g_x  [(size_t)N_NODES * D_FEAT];   // tf32-rounded x
__device__ __align__(16) float g_w1r [768 * 256];   // rounded W1 (concat over K)
__device__ __align__(16) float g_wcat[512 * 128];   // [W2_0 - W2_2 ; W2_1] rounded
__device__ __align__(16) float g_w2s [256 * 128];   // W2_2 rounded
__device__ float g_deg[N_NODES];
__device__ int   g_cnt[N_NODES];
__device__ int   g_fill[N_NODES];
__device__ int   g_rowptr[N_NODES + 1];
__device__ int   g_dst[N_EDGES];
__device__ float g_w[N_EDGES];
__device__ int   g_is64;
__device__ int   g_bsum[256];
__device__ int   g_boff[256];

// Buffer ids: 0 = external pointer, 1 = tx1, 2 = tx2, 3 = h, 4 = x_rounded.
template <int ID>
__device__ __forceinline__ float* sel_buf(float* ext) {
    if (ID == 1) return g_tx1;
    if (ID == 2) return g_tx2;
    if (ID == 3) return g_h;
    if (ID == 4) return g_x;
    return ext;
}
template <int ID>
__device__ __forceinline__ const float* sel_cbuf(const float* ext) {
    if (ID == 1) return g_tx1;
    if (ID == 2) return g_tx2;
    if (ID == 3) return g_h;
    if (ID == 4) return g_x;
    return ext;
}

__device__ __forceinline__ uint32_t f2tf32(float x) {
    uint32_t r;
    asm("cvt.rna.tf32.f32 %0, %1;" : "=r"(r) : "f"(x));
    return r;
}
__device__ __forceinline__ float rnd_tf32(float x) {
    return __uint_as_float(f2tf32(x));
}

// ---------------- dtype detection (int32 vs int64 edge_index) ----------------
__global__ void detect_kernel(const int* __restrict__ ei) {
    __shared__ int any_nonzero;
    if (threadIdx.x == 0) any_nonzero = 0;
    __syncthreads();
    for (int i = threadIdx.x; i < 2048; i += blockDim.x) {
        if (ei[2 * i + 1] != 0) { any_nonzero = 1; break; }
    }
    __syncthreads();
    if (threadIdx.x == 0) g_is64 = (any_nonzero == 0) ? 1 : 0;
}

__device__ __forceinline__ int edge_row(const int* ei, int e) {
    return g_is64 ? ei[2 * e] : ei[e];
}
__device__ __forceinline__ int edge_col(const int* ei, int e) {
    return g_is64 ? ei[2 * (N_EDGES + e)] : ei[N_EDGES + e];
}

// ---------------- CSR build ----------------
__global__ void zero_kernel() {
    int i = blockIdx.x * blockDim.x + threadIdx.x;
    if (i < N_NODES) {
        g_deg[i] = 0.f;
        g_cnt[i] = 0;
        g_fill[i] = 0;
    }
}

__global__ void deg_count_kernel(const int* __restrict__ ei,
                                 const float* __restrict__ ew) {
    int e = blockIdx.x * blockDim.x + threadIdx.x;
    if (e >= N_EDGES) return;
    int r = edge_row(ei, e);
    atomicAdd(&g_deg[r], ew[e]);
    atomicAdd(&g_cnt[r], 1);
}

__global__ void scan_pre_kernel() {
    __shared__ int red[256];
    int t = threadIdx.x;
    int i = blockIdx.x * 256 + t;
    red[t] = (i < N_NODES) ? g_cnt[i] : 0;
    __syncthreads();
    for (int off = 128; off > 0; off >>= 1) {
        if (t < off) red[t] += red[t + off];
        __syncthreads();
    }
    if (t == 0) g_bsum[blockIdx.x] = red[0];
}

__global__ void scan_mid_kernel() {
    __shared__ int s[256];
    int t = threadIdx.x;
    int v = (t < SCAN_BLOCKS) ? g_bsum[t] : 0;
    s[t] = v;
    __syncthreads();
    for (int off = 1; off < 256; off <<= 1) {
        int u = (t >= off) ? s[t - off] : 0;
        __syncthreads();
        s[t] += u;
        __syncthreads();
    }
    if (t < SCAN_BLOCKS) g_boff[t] = s[t] - v;
    if (t == 255) g_rowptr[N_NODES] = s[255];
}

__global__ void scan_post_kernel() {
    __shared__ int s[256];
    int t = threadIdx.x;
    int i = blockIdx.x * 256 + t;
    int v = (i < N_NODES) ? g_cnt[i] : 0;
    s[t] = v;
    __syncthreads();
    for (int off = 1; off < 256; off <<= 1) {
        int u = (t >= off) ? s[t - off] : 0;
        __syncthreads();
        s[t] += u;
        __syncthreads();
    }
    if (i < N_NODES) g_rowptr[i] = g_boff[blockIdx.x] + s[t] - v;
}

__global__ void build_kernel(const int* __restrict__ ei,
                             const float* __restrict__ ew) {
    int e = blockIdx.x * blockDim.x + threadIdx.x;
    if (e >= N_EDGES) return;
    int r = edge_row(ei, e);
    int c = edge_col(ei, e);
    float dr = g_deg[r], dc = g_deg[c];
    float ir = dr > 0.f ? rsqrtf(dr) : 0.f;
    float ic = dc > 0.f ? rsqrtf(dc) : 0.f;
    float w = -ir * ew[e] * ic;
    int pos = atomicAdd(&g_fill[r], 1);
    int idx = g_rowptr[r] + pos;
    g_dst[idx] = c;
    g_w[idx] = w;
}

// ---------------- pre-rounding kernels ----------------
__global__ void round_x_kernel(const float* __restrict__ x) {
    int i = blockIdx.x * blockDim.x + threadIdx.x;
    if (i >= N_NODES * D_FEAT / 4) return;
    float4 v = ((const float4*)x)[i];
    v.x = rnd_tf32(v.x); v.y = rnd_tf32(v.y);
    v.z = rnd_tf32(v.z); v.w = rnd_tf32(v.w);
    ((float4*)g_x)[i] = v;
}

__global__ void round_w_kernel(const float* __restrict__ W1,
                               const float* __restrict__ W2) {
    int i = blockIdx.x * blockDim.x + threadIdx.x;
    if (i < 768 * 256) {
        g_w1r[i] = rnd_tf32(W1[i]);
    } else if (i < 768 * 256 + 512 * 128) {
        int j = i - 768 * 256;
        int r = j >> 7, c = j & 127;
        float v = (r < 256) ? (W2[r * 128 + c] - W2[65536 + r * 128 + c])
                            : W2[32768 + (r - 256) * 128 + c];
        g_wcat[j] = rnd_tf32(v);
    } else if (i < 768 * 256 + 512 * 128 + 256 * 128) {
        int j = i - (768 * 256 + 512 * 128);
        g_w2s[j] = rnd_tf32(W2[65536 + j]);
    }
}

// ---------------- SpMM ----------------
// dst[row] = alpha * sum_e w_e * src[col_e]  + beta * sub[row]
// FW = feature width in float4-per-lane (2 -> 256 feats, 1 -> 128 feats).
// ROUND = tf32-round outputs. One warp per row, 2-edge unroll for MLP.
template <int SRC, int SUB, int DST, int FW, int ROUND>
__global__ void spmm_kernel(const float* __restrict__ ext_src,
                            const float* __restrict__ ext_sub,
                            float* __restrict__ ext_dst,
                            float alpha, float beta) {
    const float* src = sel_cbuf<SRC>(ext_src);
    float*       dst = sel_buf<DST>(ext_dst);
    const int FEATS = FW * 128;

    int warp = (blockIdx.x * blockDim.x + threadIdx.x) >> 5;
    int lane = threadIdx.x & 31;
    if (warp >= N_NODES) return;
    int s = g_rowptr[warp];
    int e = g_rowptr[warp + 1];

    float4 aA0 = make_float4(0.f, 0.f, 0.f, 0.f);
    float4 aA1 = make_float4(0.f, 0.f, 0.f, 0.f);
    float4 aB0 = make_float4(0.f, 0.f, 0.f, 0.f);
    float4 aB1 = make_float4(0.f, 0.f, 0.f, 0.f);

    int i = s;
    for (; i + 2 <= e; i += 2) {
        float w0 = g_w[i], w1 = g_w[i + 1];
        const float4* p0 = (const float4*)(src + (size_t)g_dst[i] * FEATS);
        const float4* p1 = (const float4*)(src + (size_t)g_dst[i + 1] * FEATS);
        float4 x0 = p0[lane];
        float4 y0 = p1[lane];
        aA0.x += w0 * x0.x; aA0.y += w0 * x0.y; aA0.z += w0 * x0.z; aA0.w += w0 * x0.w;
        aB0.x += w1 * y0.x; aB0.y += w1 * y0.y; aB0.z += w1 * y0.z; aB0.w += w1 * y0.w;
        if (FW == 2) {
            float4 x1 = p0[lane + 32];
            float4 y1 = p1[lane + 32];
            aA1.x += w0 * x1.x; aA1.y += w0 * x1.y; aA1.z += w0 * x1.z; aA1.w += w0 * x1.w;
            aB1.x += w1 * y1.x; aB1.y += w1 * y1.y; aB1.z += w1 * y1.z; aB1.w += w1 * y1.w;
        }
    }
    if (i < e) {
        float w0 = g_w[i];
        const float4* p0 = (const float4*)(src + (size_t)g_dst[i] * FEATS);
        float4 x0 = p0[lane];
        aA0.x += w0 * x0.x; aA0.y += w0 * x0.y; aA0.z += w0 * x0.z; aA0.w += w0 * x0.w;
        if (FW == 2) {
            float4 x1 = p0[lane + 32];
            aA1.x += w0 * x1.x; aA1.y += w0 * x1.y; aA1.z += w0 * x1.z; aA1.w += w0 * x1.w;
        }
    }
    float4 a0, a1;
    a0.x = aA0.x + aB0.x; a0.y = aA0.y + aB0.y; a0.z = aA0.z + aB0.z; a0.w = aA0.w + aB0.w;
    a1.x = aA1.x + aB1.x; a1.y = aA1.y + aB1.y; a1.z = aA1.z + aB1.z; a1.w = aA1.w + aB1.w;

    if (SUB >= 0) {
        const float* sub = sel_cbuf<(SUB >= 0 ? SUB : 0)>(ext_sub);
        const float4* sp = (const float4*)(sub + (size_t)warp * FEATS);
        float4 s0 = sp[lane];
        a0.x = alpha * a0.x + beta * s0.x; a0.y = alpha * a0.y + beta * s0.y;
        a0.z = alpha * a0.z + beta * s0.z; a0.w = alpha * a0.w + beta * s0.w;
        if (FW == 2) {
            float4 s1 = sp[lane + 32];
            a1.x = alpha * a1.x + beta * s1.x; a1.y = alpha * a1.y + beta * s1.y;
            a1.z = alpha * a1.z + beta * s1.z; a1.w = alpha * a1.w + beta * s1.w;
        }
    }
    if (ROUND) {
        a0.x = rnd_tf32(a0.x); a0.y = rnd_tf32(a0.y);
        a0.z = rnd_tf32(a0.z); a0.w = rnd_tf32(a0.w);
        if (FW == 2) {
            a1.x = rnd_tf32(a1.x); a1.y = rnd_tf32(a1.y);
            a1.z = rnd_tf32(a1.z); a1.w = rnd_tf32(a1.w);
        }
    }
    float4* op = (float4*)(dst + (size_t)warp * FEATS);
    op[lane] = a0;
    if (FW == 2) op[lane + 32] = a1;
}

// ---------------- cp.async double-buffered tf32 GEMM ----------------
// C[M,NN] = relu?( [segs] (M x NSEG*256) @ B (NSEG*256 x NN) + bias )
// All A segs and B are pre-rounded to tf32-in-fp32 -> staging is raw cp.async.
// 256 threads, 8 warps (4m x 2n), warp tile 32x64, BK=32, mma.m16n8k8.tf32.

__device__ __forceinline__ void mma_tf32(float c[4], const uint32_t a[4],
                                         const uint32_t b[2]) {
    asm volatile(
        "mma.sync.aligned.m16n8k8.row.col.f32.tf32.tf32.f32 "
        "{%0,%1,%2,%3}, {%4,%5,%6,%7}, {%8,%9}, {%0,%1,%2,%3};\n"
        : "+f"(c[0]), "+f"(c[1]), "+f"(c[2]), "+f"(c[3])
        : "r"(a[0]), "r"(a[1]), "r"(a[2]), "r"(a[3]), "r"(b[0]), "r"(b[1]));
}

__device__ __forceinline__ void cpasync16(uint32_t dst, const void* src, int srcsize) {
    asm volatile("cp.async.ca.shared.global [%0], [%1], 16, %2;\n"
                 :: "r"(dst), "l"(src), "r"(srcsize));
}
__device__ __forceinline__ void cp_commit() {
    asm volatile("cp.async.commit_group;\n" ::: "memory");
}
__device__ __forceinline__ void cp_wait1() {
    asm volatile("cp.async.wait_group 1;\n" ::: "memory");
}
__device__ __forceinline__ void cp_wait0() {
    asm volatile("cp.async.wait_group 0;\n" ::: "memory");
}

// smem float layout: As(b) = b*4608 (128x36), Bs(b) = 9216 + b*4224 (32x132)
#define GEMM_SMEM_BYTES 70656

template <int S0, int S1, int S2, int NSEG, int WID, int CID,
          int NN, int RELU, int ROUND, int BIAS>
__global__ __launch_bounds__(256, 2)
void gemm_tc(const float* __restrict__ bias, float* __restrict__ ext_c) {
    extern __shared__ float smx[];
    const float* seg0 = sel_cbuf<S0>(nullptr);
    const float* seg1 = sel_cbuf<S1>(nullptr);
    const float* seg2 = sel_cbuf<S2>(nullptr);
    const float* Bm = (WID == 1) ? g_w1r : ((WID == 2) ? g_wcat : g_w2s);
    float* C = sel_buf<CID>(ext_c);
    const int M = N_NODES;
    const int NS = NSEG * 8;

    const int tid  = threadIdx.x;
    const int lane = tid & 31;
    const int wid  = tid >> 5;
    const int g = lane >> 2;
    const int t = lane & 3;

    const int bm = blockIdx.y * 128;
    const int bn = blockIdx.x * 128;
    const int wm = (wid & 3) * 32;
    const int wn = (wid >> 2) * 64;

    const uint32_t sbase = (uint32_t)__cvta_generic_to_shared(smx);

    float acc[2][8][4];
#pragma unroll
    for (int i = 0; i < 2; i++)
#pragma unroll
        for (int j = 0; j < 8; j++)
#pragma unroll
            for (int q = 0; q < 4; q++) acc[i][j][q] = 0.f;

    auto issue = [&](int s) {
        const float* seg = (s < 8) ? seg0 : ((s < 16) ? seg1 : seg2);
        const int kb = (s & 7) * 32;
        const uint32_t aoff = sbase + (uint32_t)((s & 1) * 4608 * 4);
        const uint32_t boff = sbase + (uint32_t)((9216 + (s & 1) * 4224) * 4);
        // A tile: 128 rows x 32 k
#pragma unroll
        for (int p = 0; p < 4; p++) {
            int v = p * 256 + tid;
            int row = v >> 3, k4 = v & 7;
            int rg = bm + row;
            int ok = (rg < M);
            const float* src = seg + (size_t)(ok ? rg : 0) * D_FEAT + kb + k4 * 4;
            cpasync16(aoff + (uint32_t)((row * 36 + k4 * 4) * 4), src, ok ? 16 : 0);
        }
        // B tile: 32 k x 128 n
#pragma unroll
        for (int p = 0; p < 4; p++) {
            int v = p * 256 + tid;
            int k = v >> 5, n4 = v & 31;
            const float* src = Bm + (size_t)(s * 32 + k) * NN + bn + n4 * 4;
            cpasync16(boff + (uint32_t)((k * 132 + n4 * 4) * 4), src, 16);
        }
        cp_commit();
    };

    issue(0);
    for (int s = 0; s < NS; s++) {
        if (s + 1 < NS) { issue(s + 1); cp_wait1(); }
        else            { cp_wait0(); }
        __syncthreads();

        const float* As = smx + (s & 1) * 4608;
        const float* Bs = smx + 9216 + (s & 1) * 4224;
#pragma unroll
        for (int ks = 0; ks < 4; ks++) {
            const int k0 = ks * 8;
            uint32_t afr[2][4];
            uint32_t bfr[8][2];
#pragma unroll
            for (int i = 0; i < 2; i++) {
                int rA = wm + 16 * i + g;
                afr[i][0] = __float_as_uint(As[rA * 36 + k0 + t]);
                afr[i][1] = __float_as_uint(As[(rA + 8) * 36 + k0 + t]);
                afr[i][2] = __float_as_uint(As[rA * 36 + k0 + t + 4]);
                afr[i][3] = __float_as_uint(As[(rA + 8) * 36 + k0 + t + 4]);
            }
#pragma unroll
            for (int j = 0; j < 8; j++) {
                bfr[j][0] = __float_as_uint(Bs[(k0 + t) * 132 + wn + 8 * j + g]);
                bfr[j][1] = __float_as_uint(Bs[(k0 + t + 4) * 132 + wn + 8 * j + g]);
            }
#pragma unroll
            for (int i = 0; i < 2; i++)
#pragma unroll
                for (int j = 0; j < 8; j++)
                    mma_tf32(acc[i][j], afr[i], bfr[j]);
        }
        __syncthreads();
    }

    // epilogue
#pragma unroll
    for (int i = 0; i < 2; i++) {
        int r0 = bm + wm + 16 * i + g;
        int r1 = r0 + 8;
#pragma unroll
        for (int j = 0; j < 8; j++) {
            int col = bn + wn + 8 * j + 2 * t;
            float bb0 = BIAS ? bias[col] : 0.f;
            float bb1 = BIAS ? bias[col + 1] : 0.f;
            float v0 = acc[i][j][0] + bb0, v1 = acc[i][j][1] + bb1;
            float v2 = acc[i][j][2] + bb0, v3 = acc[i][j][3] + bb1;
            if (RELU) {
                v0 = fmaxf(v0, 0.f); v1 = fmaxf(v1, 0.f);
                v2 = fmaxf(v2, 0.f); v3 = fmaxf(v3, 0.f);
            }
            if (ROUND) {
                v0 = rnd_tf32(v0); v1 = rnd_tf32(v1);
                v2 = rnd_tf32(v2); v3 = rnd_tf32(v3);
            }
            if (r0 < M) *(float2*)(C + (size_t)r0 * NN + col) = make_float2(v0, v1);
            if (r1 < M) *(float2*)(C + (size_t)r1 * NN + col) = make_float2(v2, v3);
        }
    }
}

// ---------------- launch ----------------

extern "C" void kernel_launch(void* const* d_in, const int* in_sizes, int n_in,
                              void* d_out, int out_size) {
    const float* x  = (const float*)d_in[0];
    const int*   ei = (const int*)d_in[1];
    const float* ew = (const float*)d_in[2];
    const float* W1 = (const float*)d_in[3];   // [3,256,256]
    const float* b1 = (const float*)d_in[4];
    const float* W2 = (const float*)d_in[5];   // [3,256,128]
    const float* b2 = (const float*)d_in[6];
    float*       out = (float*)d_out;

    // GEMM instantiations + dynamic smem opt-in (non-stream API; not captured)
    auto* gL1  = gemm_tc<4, 1, 2, 3, 1, 3, 256, 1, 1, 1>;  // h = relu([x|tx1|tx2]@W1r+b1), rounded
    auto* gP   = gemm_tc<1, 1, 1, 1, 3, 2, 128, 0, 0, 0>;  // P = Z@W2_2 -> tx2
    auto* gOut = gemm_tc<3, 1, 1, 2, 2, 0, 128, 0, 0, 1>;  // out = [h|Z]@wcat + b2
    cudaFuncSetAttribute(gL1,  cudaFuncAttributeMaxDynamicSharedMemorySize, GEMM_SMEM_BYTES);
    cudaFuncSetAttribute(gP,   cudaFuncAttributeMaxDynamicSharedMemorySize, GEMM_SMEM_BYTES);
    cudaFuncSetAttribute(gOut, cudaFuncAttributeMaxDynamicSharedMemorySize, GEMM_SMEM_BYTES);

    // CSR build + pre-rounding
    detect_kernel<<<1, 256>>>(ei);
    zero_kernel<<<SCAN_BLOCKS, 256>>>();
    deg_count_kernel<<<(N_EDGES + 255) / 256, 256>>>(ei, ew);
    scan_pre_kernel<<<SCAN_BLOCKS, 256>>>();
    scan_mid_kernel<<<1, 256>>>();
    scan_post_kernel<<<SCAN_BLOCKS, 256>>>();
    build_kernel<<<(N_EDGES + 255) / 256, 256>>>(ei, ew);
    round_x_kernel<<<(N_NODES * D_FEAT / 4 + 255) / 256, 256>>>(x);
    round_w_kernel<<<(768 * 256 + 512 * 128 + 256 * 128 + 255) / 256, 256>>>(W1, W2);

    const int spmm_blocks = (N_NODES * 32 + 255) / 256;
    const dim3 g256(2, (N_NODES + 127) / 128);
    const dim3 g128(1, (N_NODES + 127) / 128);

    // ---- layer 1 ----
    // tx1 = L @ x   (rounded)
    spmm_kernel<4, -1, 1, 2, 1><<<spmm_blocks, 256>>>(nullptr, nullptr, nullptr, 1.f, 0.f);
    // tx2 = 2*L@tx1 - x   (rounded)
    spmm_kernel<1, 4, 2, 2, 1><<<spmm_blocks, 256>>>(nullptr, nullptr, nullptr, 2.f, -1.f);
    // h = relu([x|tx1|tx2] @ W1 + b1)   (rounded)
    gL1<<<g256, 256, GEMM_SMEM_BYTES>>>(b1, nullptr);

    // ---- layer 2 (commuted) ----
    // Z = L @ h -> tx1   (rounded)
    spmm_kernel<3, -1, 1, 2, 1><<<spmm_blocks, 256>>>(nullptr, nullptr, nullptr, 1.f, 0.f);
    // P = Z @ W2[2] -> tx2 (raw fp32)
    gP<<<g128, 256, GEMM_SMEM_BYTES>>>(nullptr, nullptr);
    // out = [h|Z] @ [W2[0]-W2[2]; W2[1]] + b2
    gOut<<<g128, 256, GEMM_SMEM_BYTES>>>(b2, out);
    // out += 2 * L @ P   (128-wide, no rounding)
    spmm_kernel<2, 0, 0, 1, 0><<<spmm_blocks, 256>>>(nullptr, out, out, 2.f, 1.f);

    (void)in_sizes; (void)n_in; (void)out_size;
}

// round 10
// speedup vs baseline: 3.8790x; 1.5075x over previous
#include <cuda_runtime.h>
#include <cuda_fp16.h>
#include <cstdint>
#include <cstddef>

// Problem constants (fixed by the reference)
#define N_NODES 50000
#define N_EDGES 312500
#define SCAN_BLOCKS 196         // 196 * 256 = 50176 >= N_NODES

// ---------------- scratch (static device globals; no allocation) ----------------
__device__ __align__(16) __half g_x  [(size_t)N_NODES * 256];
__device__ __align__(16) __half g_tx1[(size_t)N_NODES * 256];
__device__ __align__(16) __half g_tx2[(size_t)N_NODES * 256];
__device__ __align__(16) __half g_h  [(size_t)N_NODES * 256];
__device__ __align__(16) __half g_p  [(size_t)N_NODES * 128];
__device__ __align__(16) __half g_w1t[256 * 768];   // W1^T [n][k]
__device__ __align__(16) __half g_w2t[256 * 512];   // fused layer-2 B^T [n][k]
__device__ float g_deg[N_NODES];
__device__ int   g_cnt[N_NODES];
__device__ int   g_fill[N_NODES];
__device__ int   g_rowptr[N_NODES + 1];
__device__ int   g_dst[N_EDGES];
__device__ float g_w[N_EDGES];
__device__ int   g_is64;
__device__ int   g_bsum[256];
__device__ int   g_boff[256];

// Buffer ids: 1 = tx1, 2 = tx2, 3 = h, 4 = x, 5 = p.
template <int ID>
__device__ __forceinline__ const __half* hbuf() {
    if (ID == 1) return g_tx1;
    if (ID == 2) return g_tx2;
    if (ID == 3) return g_h;
    if (ID == 4) return g_x;
    return g_p;
}
template <int ID>
__device__ __forceinline__ __half* hbuf_w() {
    if (ID == 1) return g_tx1;
    if (ID == 2) return g_tx2;
    if (ID == 3) return g_h;
    if (ID == 4) return g_x;
    return g_p;
}

// ---------------- cp.async ----------------
__device__ __forceinline__ void cpasync16(uint32_t dst, const void* src, int srcsize) {
    asm volatile("cp.async.ca.shared.global [%0], [%1], 16, %2;\n"
                 :: "r"(dst), "l"(src), "r"(srcsize));
}
__device__ __forceinline__ void cp_commit() {
    asm volatile("cp.async.commit_group;\n" ::: "memory");
}
__device__ __forceinline__ void cp_wait1() {
    asm volatile("cp.async.wait_group 1;\n" ::: "memory");
}
__device__ __forceinline__ void cp_wait0() {
    asm volatile("cp.async.wait_group 0;\n" ::: "memory");
}

// ---------------- fp16 mma ----------------
__device__ __forceinline__ void mma_f16(float c[4], const uint32_t a[4],
                                        const uint32_t b[2]) {
    asm volatile(
        "mma.sync.aligned.m16n8k16.row.col.f32.f16.f16.f32 "
        "{%0,%1,%2,%3}, {%4,%5,%6,%7}, {%8,%9}, {%0,%1,%2,%3};\n"
        : "+f"(c[0]), "+f"(c[1]), "+f"(c[2]), "+f"(c[3])
        : "r"(a[0]), "r"(a[1]), "r"(a[2]), "r"(a[3]), "r"(b[0]), "r"(b[1]));
}

// ---------------- dtype detection (int32 vs int64 edge_index) ----------------
__global__ void detect_kernel(const int* __restrict__ ei) {
    __shared__ int any_nonzero;
    if (threadIdx.x == 0) any_nonzero = 0;
    __syncthreads();
    for (int i = threadIdx.x; i < 2048; i += blockDim.x) {
        if (ei[2 * i + 1] != 0) { any_nonzero = 1; break; }
    }
    __syncthreads();
    if (threadIdx.x == 0) g_is64 = (any_nonzero == 0) ? 1 : 0;
}

__device__ __forceinline__ int edge_row(const int* ei, int e) {
    return g_is64 ? ei[2 * e] : ei[e];
}
__device__ __forceinline__ int edge_col(const int* ei, int e) {
    return g_is64 ? ei[2 * (N_EDGES + e)] : ei[N_EDGES + e];
}

// ---------------- CSR build ----------------
__global__ void zero_kernel() {
    int i = blockIdx.x * blockDim.x + threadIdx.x;
    if (i < N_NODES) {
        g_deg[i] = 0.f;
        g_cnt[i] = 0;
        g_fill[i] = 0;
    }
}

__global__ void deg_count_kernel(const int* __restrict__ ei,
                                 const float* __restrict__ ew) {
    int e = blockIdx.x * blockDim.x + threadIdx.x;
    if (e >= N_EDGES) return;
    int r = edge_row(ei, e);
    atomicAdd(&g_deg[r], ew[e]);
    atomicAdd(&g_cnt[r], 1);
}

__global__ void scan_pre_kernel() {
    __shared__ int red[256];
    int t = threadIdx.x;
    int i = blockIdx.x * 256 + t;
    red[t] = (i < N_NODES) ? g_cnt[i] : 0;
    __syncthreads();
    for (int off = 128; off > 0; off >>= 1) {
        if (t < off) red[t] += red[t + off];
        __syncthreads();
    }
    if (t == 0) g_bsum[blockIdx.x] = red[0];
}

__global__ void scan_mid_kernel() {
    __shared__ int s[256];
    int t = threadIdx.x;
    int v = (t < SCAN_BLOCKS) ? g_bsum[t] : 0;
    s[t] = v;
    __syncthreads();
    for (int off = 1; off < 256; off <<= 1) {
        int u = (t >= off) ? s[t - off] : 0;
        __syncthreads();
        s[t] += u;
        __syncthreads();
    }
    if (t < SCAN_BLOCKS) g_boff[t] = s[t] - v;
    if (t == 255) g_rowptr[N_NODES] = s[255];
}

__global__ void scan_post_kernel() {
    __shared__ int s[256];
    int t = threadIdx.x;
    int i = blockIdx.x * 256 + t;
    int v = (i < N_NODES) ? g_cnt[i] : 0;
    s[t] = v;
    __syncthreads();
    for (int off = 1; off < 256; off <<= 1) {
        int u = (t >= off) ? s[t - off] : 0;
        __syncthreads();
        s[t] += u;
        __syncthreads();
    }
    if (i < N_NODES) g_rowptr[i] = g_boff[blockIdx.x] + s[t] - v;
}

__global__ void build_kernel(const int* __restrict__ ei,
                             const float* __restrict__ ew) {
    int e = blockIdx.x * blockDim.x + threadIdx.x;
    if (e >= N_EDGES) return;
    int r = edge_row(ei, e);
    int c = edge_col(ei, e);
    float dr = g_deg[r], dc = g_deg[c];
    float ir = dr > 0.f ? rsqrtf(dr) : 0.f;
    float ic = dc > 0.f ? rsqrtf(dc) : 0.f;
    float w = -ir * ew[e] * ic;
    int pos = atomicAdd(&g_fill[r], 1);
    int idx = g_rowptr[r] + pos;
    g_dst[idx] = c;
    g_w[idx] = w;
}

// ---------------- conversion / weight prep ----------------
__global__ void conv_x_kernel(const float* __restrict__ x) {
    int i = blockIdx.x * blockDim.x + threadIdx.x;
    if (i >= N_NODES * 256 / 4) return;
    float4 v = ((const float4*)x)[i];
    __half2 h0 = __floats2half2_rn(v.x, v.y);
    __half2 h1 = __floats2half2_rn(v.z, v.w);
    uint2 o;
    o.x = *(uint32_t*)&h0;
    o.y = *(uint32_t*)&h1;
    ((uint2*)g_x)[i] = o;
}

// g_w1t[n*768+k] = W1[k][n];  g_w2t[n*512+k] = fused layer-2 weight^T
//   n<128 :  k<256 -> W2_0[k][n] - W2_2[k][n]; k>=256 -> W2_1[k-256][n]
//   n>=128:  k<256 -> 0;                        k>=256 -> W2_2[k-256][n-128]
__global__ void prep_w_kernel(const float* __restrict__ W1,
                              const float* __restrict__ W2) {
    int i = blockIdx.x * blockDim.x + threadIdx.x;
    if (i < 256 * 768) {
        int n = i / 768, k = i % 768;
        g_w1t[i] = __float2half_rn(W1[k * 256 + n]);
    } else if (i < 256 * 768 + 256 * 512) {
        int j = i - 256 * 768;
        int n = j / 512, k = j % 512;
        float v;
        if (n < 128) {
            v = (k < 256) ? (W2[k * 128 + n] - W2[65536 + k * 128 + n])
                          : W2[32768 + (k - 256) * 128 + n];
        } else {
            v = (k < 256) ? 0.f : W2[65536 + (k - 256) * 128 + (n - 128)];
        }
        g_w2t[j] = __float2half_rn(v);
    }
}

// ---------------- fp16 SpMM (256-wide) ----------------
// dst[row] = alpha * sum_e w_e * src[col_e] + beta * sub[row]; fp32 accumulate.
__device__ __forceinline__ void acc8(float* a, uint4 u, float w) {
    float2 f;
    f = __half22float2(*(__half2*)&u.x); a[0] += w * f.x; a[1] += w * f.y;
    f = __half22float2(*(__half2*)&u.y); a[2] += w * f.x; a[3] += w * f.y;
    f = __half22float2(*(__half2*)&u.z); a[4] += w * f.x; a[5] += w * f.y;
    f = __half22float2(*(__half2*)&u.w); a[6] += w * f.x; a[7] += w * f.y;
}

template <int SRC, int SUB, int DST>
__global__ __launch_bounds__(256)
void spmm256_kernel(float alpha, float beta) {
    const __half* src = hbuf<SRC>();
    __half*       dst = hbuf_w<DST>();

    int warp = (blockIdx.x * blockDim.x + threadIdx.x) >> 5;
    int lane = threadIdx.x & 31;
    if (warp >= N_NODES) return;
    int s = g_rowptr[warp];
    int e = g_rowptr[warp + 1];

    float aA[8] = {0, 0, 0, 0, 0, 0, 0, 0};
    float aB[8] = {0, 0, 0, 0, 0, 0, 0, 0};

    int i = s;
    for (; i + 2 <= e; i += 2) {
        float w0 = g_w[i], w1 = g_w[i + 1];
        uint4 u0 = ((const uint4*)(src + (size_t)g_dst[i] * 256))[lane];
        uint4 u1 = ((const uint4*)(src + (size_t)g_dst[i + 1] * 256))[lane];
        acc8(aA, u0, w0);
        acc8(aB, u1, w1);
    }
    if (i < e) {
        uint4 u0 = ((const uint4*)(src + (size_t)g_dst[i] * 256))[lane];
        acc8(aA, u0, g_w[i]);
    }
    float a[8];
#pragma unroll
    for (int j = 0; j < 8; j++) a[j] = aA[j] + aB[j];

    if (SUB >= 0) {
        const __half* sub = hbuf<(SUB >= 0 ? SUB : 1)>();
        uint4 su = ((const uint4*)(sub + (size_t)warp * 256))[lane];
        float sv[8];
        float2 f;
        f = __half22float2(*(__half2*)&su.x); sv[0] = f.x; sv[1] = f.y;
        f = __half22float2(*(__half2*)&su.y); sv[2] = f.x; sv[3] = f.y;
        f = __half22float2(*(__half2*)&su.z); sv[4] = f.x; sv[5] = f.y;
        f = __half22float2(*(__half2*)&su.w); sv[6] = f.x; sv[7] = f.y;
#pragma unroll
        for (int j = 0; j < 8; j++) a[j] = alpha * a[j] + beta * sv[j];
    }

    uint4 o;
    __half2 h;
    h = __floats2half2_rn(a[0], a[1]); o.x = *(uint32_t*)&h;
    h = __floats2half2_rn(a[2], a[3]); o.y = *(uint32_t*)&h;
    h = __floats2half2_rn(a[4], a[5]); o.z = *(uint32_t*)&h;
    h = __floats2half2_rn(a[6], a[7]); o.w = *(uint32_t*)&h;
    ((uint4*)(dst + (size_t)warp * 256))[lane] = o;
}

// ---------------- final SpMM: out(f32) += 2 * L @ P (P half, 128-wide) ----------------
__global__ __launch_bounds__(256)
void spmm_out_kernel(float* __restrict__ out) {
    int warp = (blockIdx.x * blockDim.x + threadIdx.x) >> 5;
    int lane = threadIdx.x & 31;
    if (warp >= N_NODES) return;
    int s = g_rowptr[warp];
    int e = g_rowptr[warp + 1];

    float aA[4] = {0, 0, 0, 0};
    float aB[4] = {0, 0, 0, 0};
    int i = s;
    for (; i + 2 <= e; i += 2) {
        float w0 = g_w[i], w1 = g_w[i + 1];
        uint2 u0 = ((const uint2*)(g_p + (size_t)g_dst[i] * 128))[lane];
        uint2 u1 = ((const uint2*)(g_p + (size_t)g_dst[i + 1] * 128))[lane];
        float2 f;
        f = __half22float2(*(__half2*)&u0.x); aA[0] += w0 * f.x; aA[1] += w0 * f.y;
        f = __half22float2(*(__half2*)&u0.y); aA[2] += w0 * f.x; aA[3] += w0 * f.y;
        f = __half22float2(*(__half2*)&u1.x); aB[0] += w1 * f.x; aB[1] += w1 * f.y;
        f = __half22float2(*(__half2*)&u1.y); aB[2] += w1 * f.x; aB[3] += w1 * f.y;
    }
    if (i < e) {
        float w0 = g_w[i];
        uint2 u0 = ((const uint2*)(g_p + (size_t)g_dst[i] * 128))[lane];
        float2 f;
        f = __half22float2(*(__half2*)&u0.x); aA[0] += w0 * f.x; aA[1] += w0 * f.y;
        f = __half22float2(*(__half2*)&u0.y); aA[2] += w0 * f.x; aA[3] += w0 * f.y;
    }
    float4* op = (float4*)(out + (size_t)warp * 128) + lane;
    float4 o = *op;
    o.x += 2.f * (aA[0] + aB[0]);
    o.y += 2.f * (aA[1] + aB[1]);
    o.z += 2.f * (aA[2] + aB[2]);
    o.w += 2.f * (aA[3] + aB[3]);
    *op = o;
}

// ---------------- fp16 mma GEMM, cp.async double-buffered ----------------
// Block 128(M) x 128(N), 256 threads, 8 warps (4m x 2n), warp tile 32x64,
// BK = 32 halfs, mma.m16n8k16. Static smem 40KB.
// LAYER 1: A=[x|tx1|tx2] (K=768), B=g_w1t, out=h (half, bias+relu).
// LAYER 2: A=[h|Z=tx1] (K=512), B=g_w2t, global col<128 -> out(f32,+b2),
//          col>=128 -> P (half).

template <int LAYER>
__global__ __launch_bounds__(256, 2)
void gemm_h(const float* __restrict__ bias, float* __restrict__ ext_out) {
    const int K  = (LAYER == 1) ? 768 : 512;
    const int NS = K / 32;

    __shared__ __align__(16) __half As[2][128][40];
    __shared__ __align__(16) __half Bs[2][128][40];

    const int tid  = threadIdx.x;
    const int lane = tid & 31;
    const int wid  = tid >> 5;
    const int g = lane >> 2;
    const int t = lane & 3;

    const int bm = blockIdx.y * 128;
    const int bn = blockIdx.x * 128;
    const int wm = (wid & 3) * 32;
    const int wn = (wid >> 2) * 64;

    float acc[2][8][4];
#pragma unroll
    for (int i = 0; i < 2; i++)
#pragma unroll
        for (int j = 0; j < 8; j++)
#pragma unroll
            for (int q = 0; q < 4; q++) acc[i][j][q] = 0.f;

    auto issue = [&](int s) {
        const int buf = s & 1;
        const __half* seg;
        if (LAYER == 1) seg = (s < 8) ? g_x : ((s < 16) ? g_tx1 : g_tx2);
        else            seg = (s < 8) ? g_h : g_tx1;
        const __half* Bt = (LAYER == 1) ? g_w1t : g_w2t;
        const int kb = (s & 7) * 32;
#pragma unroll
        for (int p = 0; p < 2; p++) {
            int v = p * 256 + tid;
            int row = v >> 2, c = v & 3;
            int rg = bm + row;
            int ok = (rg < N_NODES) ? 16 : 0;
            const __half* src = seg + (size_t)(ok ? rg : 0) * 256 + kb + c * 8;
            cpasync16((uint32_t)__cvta_generic_to_shared(&As[buf][row][c * 8]), src, ok);
        }
#pragma unroll
        for (int p = 0; p < 2; p++) {
            int v = p * 256 + tid;
            int n = v >> 2, c = v & 3;
            const __half* src = Bt + (size_t)(bn + n) * K + s * 32 + c * 8;
            cpasync16((uint32_t)__cvta_generic_to_shared(&Bs[buf][n][c * 8]), src, 16);
        }
        cp_commit();
    };

    issue(0);
    issue(1);

    for (int s = 0; s < NS; s++) {
        if (s + 1 < NS) cp_wait1(); else cp_wait0();
        __syncthreads();
        const int buf = s & 1;
#pragma unroll
        for (int ks = 0; ks < 2; ks++) {
            const int k0 = ks * 16;
            uint32_t a[2][4];
            uint32_t b[8][2];
#pragma unroll
            for (int i = 0; i < 2; i++) {
                int r = wm + 16 * i + g;
                a[i][0] = *(const uint32_t*)&As[buf][r][k0 + 2 * t];
                a[i][1] = *(const uint32_t*)&As[buf][r + 8][k0 + 2 * t];
                a[i][2] = *(const uint32_t*)&As[buf][r][k0 + 2 * t + 8];
                a[i][3] = *(const uint32_t*)&As[buf][r + 8][k0 + 2 * t + 8];
            }
#pragma unroll
            for (int j = 0; j < 8; j++) {
                int n = wn + 8 * j + g;
                b[j][0] = *(const uint32_t*)&Bs[buf][n][k0 + 2 * t];
                b[j][1] = *(const uint32_t*)&Bs[buf][n][k0 + 2 * t + 8];
            }
#pragma unroll
            for (int i = 0; i < 2; i++)
#pragma unroll
                for (int j = 0; j < 8; j++)
                    mma_f16(acc[i][j], a[i], b[j]);
        }
        __syncthreads();
        if (s + 2 < NS) issue(s + 2);
    }

    // ---- epilogue ----
#pragma unroll
    for (int i = 0; i < 2; i++) {
        int r0 = bm + wm + 16 * i + g;
        int r1 = r0 + 8;
#pragma unroll
        for (int j = 0; j < 8; j++) {
            int col = bn + wn + 8 * j + 2 * t;
            float v0 = acc[i][j][0], v1 = acc[i][j][1];
            float v2 = acc[i][j][2], v3 = acc[i][j][3];
            if (LAYER == 1) {
                float bb0 = bias[col], bb1 = bias[col + 1];
                v0 = fmaxf(v0 + bb0, 0.f); v1 = fmaxf(v1 + bb1, 0.f);
                v2 = fmaxf(v2 + bb0, 0.f); v3 = fmaxf(v3 + bb1, 0.f);
                __half2 h01 = __floats2half2_rn(v0, v1);
                __half2 h23 = __floats2half2_rn(v2, v3);
                if (r0 < N_NODES) *(uint32_t*)(g_h + (size_t)r0 * 256 + col) = *(uint32_t*)&h01;
                if (r1 < N_NODES) *(uint32_t*)(g_h + (size_t)r1 * 256 + col) = *(uint32_t*)&h23;
            } else {
                if (col < 128) {
                    float bb0 = bias[col], bb1 = bias[col + 1];
                    if (r0 < N_NODES)
                        *(float2*)(ext_out + (size_t)r0 * 128 + col) = make_float2(v0 + bb0, v1 + bb1);
                    if (r1 < N_NODES)
                        *(float2*)(ext_out + (size_t)r1 * 128 + col) = make_float2(v2 + bb0, v3 + bb1);
                } else {
                    int pc = col - 128;
                    __half2 h01 = __floats2half2_rn(v0, v1);
                    __half2 h23 = __floats2half2_rn(v2, v3);
                    if (r0 < N_NODES) *(uint32_t*)(g_p + (size_t)r0 * 128 + pc) = *(uint32_t*)&h01;
                    if (r1 < N_NODES) *(uint32_t*)(g_p + (size_t)r1 * 128 + pc) = *(uint32_t*)&h23;
                }
            }
        }
    }
}

// ---------------- launch ----------------

extern "C" void kernel_launch(void* const* d_in, const int* in_sizes, int n_in,
                              void* d_out, int out_size) {
    const float* x  = (const float*)d_in[0];
    const int*   ei = (const int*)d_in[1];
    const float* ew = (const float*)d_in[2];
    const float* W1 = (const float*)d_in[3];   // [3,256,256]
    const float* b1 = (const float*)d_in[4];
    const float* W2 = (const float*)d_in[5];   // [3,256,128]
    const float* b2 = (const float*)d_in[6];
    float*       out = (float*)d_out;

    // CSR build + conversions
    detect_kernel<<<1, 256>>>(ei);
    zero_kernel<<<SCAN_BLOCKS, 256>>>();
    deg_count_kernel<<<(N_EDGES + 255) / 256, 256>>>(ei, ew);
    scan_pre_kernel<<<SCAN_BLOCKS, 256>>>();
    scan_mid_kernel<<<1, 256>>>();
    scan_post_kernel<<<SCAN_BLOCKS, 256>>>();
    build_kernel<<<(N_EDGES + 255) / 256, 256>>>(ei, ew);
    conv_x_kernel<<<(N_NODES * 256 / 4 + 255) / 256, 256>>>(x);
    prep_w_kernel<<<(256 * 768 + 256 * 512 + 255) / 256, 256>>>(W1, W2);

    const int spmm_blocks = (N_NODES * 32 + 255) / 256;
    const dim3 ggrid(2, (N_NODES + 127) / 128);   // N=256 for both layers

    // ---- layer 1 ----
    spmm256_kernel<4, -1, 1><<<spmm_blocks, 256>>>(1.f, 0.f);   // tx1 = L @ x
    spmm256_kernel<1, 4, 2><<<spmm_blocks, 256>>>(2.f, -1.f);   // tx2 = 2 L tx1 - x
    gemm_h<1><<<ggrid, 256>>>(b1, nullptr);                     // h

    // ---- layer 2 (commuted + fused) ----
    spmm256_kernel<3, -1, 1><<<spmm_blocks, 256>>>(1.f, 0.f);   // Z = L @ h -> tx1
    gemm_h<2><<<ggrid, 256>>>(b2, out);                         // [out_partial | P]
    spmm_out_kernel<<<spmm_blocks, 256>>>(out);                 // out += 2 L P

    (void)in_sizes; (void)n_in; (void)out_size;
}

// round 11
// speedup vs baseline: 4.0803x; 1.0519x over previous
#include <cuda_runtime.h>
#include <cuda_fp16.h>
#include <cstdint>
#include <cstddef>

// Problem constants (fixed by the reference)
#define N_NODES 50000
#define N_EDGES 312500
#define SCAN_BLOCKS 196         // 196 * 256 = 50176 >= N_NODES

// ---------------- scratch (static device globals; no allocation) ----------------
__device__ __align__(16) __half g_x  [(size_t)N_NODES * 256];
__device__ __align__(16) __half g_tx1[(size_t)N_NODES * 256];
__device__ __align__(16) __half g_tx2[(size_t)N_NODES * 256];
__device__ __align__(16) __half g_h  [(size_t)N_NODES * 256];
__device__ __align__(16) __half g_p  [(size_t)N_NODES * 128];
__device__ __align__(16) __half g_w1t[256 * 768];   // W1^T [n][k]
__device__ __align__(16) __half g_w2t[256 * 512];   // fused layer-2 B^T [n][k]
__device__ float g_deg[N_NODES];
__device__ int   g_cnt[N_NODES];
__device__ int   g_fill[N_NODES];
__device__ int   g_rowptr[N_NODES + 1];
__device__ int   g_dst[N_EDGES];
__device__ float g_w[N_EDGES];
__device__ int   g_is64;
__device__ int   g_bsum[256];
__device__ int   g_boff[256];

// Buffer ids: 1 = tx1, 2 = tx2, 3 = h, 4 = x, 5 = p.
template <int ID>
__device__ __forceinline__ const __half* hbuf() {
    if (ID == 1) return g_tx1;
    if (ID == 2) return g_tx2;
    if (ID == 3) return g_h;
    if (ID == 4) return g_x;
    return g_p;
}
template <int ID>
__device__ __forceinline__ __half* hbuf_w() {
    if (ID == 1) return g_tx1;
    if (ID == 2) return g_tx2;
    if (ID == 3) return g_h;
    if (ID == 4) return g_x;
    return g_p;
}

// ---------------- cp.async ----------------
__device__ __forceinline__ void cpasync16(uint32_t dst, const void* src, int srcsize) {
    asm volatile("cp.async.ca.shared.global [%0], [%1], 16, %2;\n"
                 :: "r"(dst), "l"(src), "r"(srcsize));
}
__device__ __forceinline__ void cp_commit() {
    asm volatile("cp.async.commit_group;\n" ::: "memory");
}
__device__ __forceinline__ void cp_wait1() {
    asm volatile("cp.async.wait_group 1;\n" ::: "memory");
}
__device__ __forceinline__ void cp_wait0() {
    asm volatile("cp.async.wait_group 0;\n" ::: "memory");
}

// ---------------- fp16 mma ----------------
__device__ __forceinline__ void mma_f16(float c[4], const uint32_t a[4],
                                        const uint32_t b[2]) {
    asm volatile(
        "mma.sync.aligned.m16n8k16.row.col.f32.f16.f16.f32 "
        "{%0,%1,%2,%3}, {%4,%5,%6,%7}, {%8,%9}, {%0,%1,%2,%3};\n"
        : "+f"(c[0]), "+f"(c[1]), "+f"(c[2]), "+f"(c[3])
        : "r"(a[0]), "r"(a[1]), "r"(a[2]), "r"(a[3]), "r"(b[0]), "r"(b[1]));
}

// ---------------- edge-index accessors ----------------
__device__ __forceinline__ int edge_row(const int* ei, int e) {
    return g_is64 ? ei[2 * e] : ei[e];
}
__device__ __forceinline__ int edge_col(const int* ei, int e) {
    return g_is64 ? ei[2 * (N_EDGES + e)] : ei[N_EDGES + e];
}

// ---------------- merged init: zero counters + dtype detect ----------------
__global__ void init_kernel(const int* __restrict__ ei) {
    int i = blockIdx.x * 256 + threadIdx.x;
    if (i < N_NODES) {
        g_deg[i] = 0.f;
        g_cnt[i] = 0;
        g_fill[i] = 0;
    }
    if (blockIdx.x == 0) {
        __shared__ int any_nonzero;
        if (threadIdx.x == 0) any_nonzero = 0;
        __syncthreads();
        for (int j = threadIdx.x; j < 2048; j += 256) {
            if (ei[2 * j + 1] != 0) { any_nonzero = 1; break; }
        }
        __syncthreads();
        if (threadIdx.x == 0) g_is64 = (any_nonzero == 0) ? 1 : 0;
    }
}

// ---------------- merged prep: conv_x + deg_count + weight prep ----------------
// grid = 12500 blocks x 256 (driven by conv_x size); other tasks bounded by i.
__global__ void prep_kernel(const int* __restrict__ ei,
                            const float* __restrict__ ew,
                            const float* __restrict__ x,
                            const float* __restrict__ W1,
                            const float* __restrict__ W2) {
    int i = blockIdx.x * 256 + threadIdx.x;

    // Task 1: x -> half (uint2 = 4 halfs each; N_NODES*64 items)
    if (i < N_NODES * 64) {
        float4 v = ((const float4*)x)[i];
        __half2 h0 = __floats2half2_rn(v.x, v.y);
        __half2 h1 = __floats2half2_rn(v.z, v.w);
        uint2 o;
        o.x = *(uint32_t*)&h0;
        o.y = *(uint32_t*)&h1;
        ((uint2*)g_x)[i] = o;
    }
    // Task 2: degree + count
    if (i < N_EDGES) {
        int r = edge_row(ei, i);
        atomicAdd(&g_deg[r], ew[i]);
        atomicAdd(&g_cnt[r], 1);
    }
    // Task 3: weight transpose/fold to half
    if (i < 256 * 768) {
        int n = i / 768, k = i % 768;
        g_w1t[i] = __float2half_rn(W1[k * 256 + n]);
    } else if (i < 256 * 768 + 256 * 512) {
        int j = i - 256 * 768;
        int n = j / 512, k = j % 512;
        float v;
        if (n < 128) {
            v = (k < 256) ? (W2[k * 128 + n] - W2[65536 + k * 128 + n])
                          : W2[32768 + (k - 256) * 128 + n];
        } else {
            v = (k < 256) ? 0.f : W2[65536 + (k - 256) * 128 + (n - 128)];
        }
        g_w2t[j] = __float2half_rn(v);
    }
}

// ---------------- decomposed scan ----------------
__global__ void scan_pre_kernel() {
    __shared__ int red[256];
    int t = threadIdx.x;
    int i = blockIdx.x * 256 + t;
    red[t] = (i < N_NODES) ? g_cnt[i] : 0;
    __syncthreads();
    for (int off = 128; off > 0; off >>= 1) {
        if (t < off) red[t] += red[t + off];
        __syncthreads();
    }
    if (t == 0) g_bsum[blockIdx.x] = red[0];
}

__global__ void scan_mid_kernel() {
    __shared__ int s[256];
    int t = threadIdx.x;
    int v = (t < SCAN_BLOCKS) ? g_bsum[t] : 0;
    s[t] = v;
    __syncthreads();
    for (int off = 1; off < 256; off <<= 1) {
        int u = (t >= off) ? s[t - off] : 0;
        __syncthreads();
        s[t] += u;
        __syncthreads();
    }
    if (t < SCAN_BLOCKS) g_boff[t] = s[t] - v;
    if (t == 255) g_rowptr[N_NODES] = s[255];
}

__global__ void scan_post_kernel() {
    __shared__ int s[256];
    int t = threadIdx.x;
    int i = blockIdx.x * 256 + t;
    int v = (i < N_NODES) ? g_cnt[i] : 0;
    s[t] = v;
    __syncthreads();
    for (int off = 1; off < 256; off <<= 1) {
        int u = (t >= off) ? s[t - off] : 0;
        __syncthreads();
        s[t] += u;
        __syncthreads();
    }
    if (i < N_NODES) g_rowptr[i] = g_boff[blockIdx.x] + s[t] - v;
}

__global__ void build_kernel(const int* __restrict__ ei,
                             const float* __restrict__ ew) {
    int e = blockIdx.x * blockDim.x + threadIdx.x;
    if (e >= N_EDGES) return;
    int r = edge_row(ei, e);
    int c = edge_col(ei, e);
    float dr = g_deg[r], dc = g_deg[c];
    float ir = dr > 0.f ? rsqrtf(dr) : 0.f;
    float ic = dc > 0.f ? rsqrtf(dc) : 0.f;
    float w = -ir * ew[e] * ic;
    int pos = atomicAdd(&g_fill[r], 1);
    int idx = g_rowptr[r] + pos;
    g_dst[idx] = c;
    g_w[idx] = w;
}

// ---------------- fp16 SpMM (256-wide) ----------------
__device__ __forceinline__ void acc8(float* a, uint4 u, float w) {
    float2 f;
    f = __half22float2(*(__half2*)&u.x); a[0] += w * f.x; a[1] += w * f.y;
    f = __half22float2(*(__half2*)&u.y); a[2] += w * f.x; a[3] += w * f.y;
    f = __half22float2(*(__half2*)&u.z); a[4] += w * f.x; a[5] += w * f.y;
    f = __half22float2(*(__half2*)&u.w); a[6] += w * f.x; a[7] += w * f.y;
}

template <int SRC, int SUB, int DST>
__global__ __launch_bounds__(256)
void spmm256_kernel(float alpha, float beta) {
    const __half* src = hbuf<SRC>();
    __half*       dst = hbuf_w<DST>();

    int warp = (blockIdx.x * blockDim.x + threadIdx.x) >> 5;
    int lane = threadIdx.x & 31;
    if (warp >= N_NODES) return;
    int s = g_rowptr[warp];
    int e = g_rowptr[warp + 1];

    float aA[8] = {0, 0, 0, 0, 0, 0, 0, 0};
    float aB[8] = {0, 0, 0, 0, 0, 0, 0, 0};

    int i = s;
    for (; i + 2 <= e; i += 2) {
        float w0 = g_w[i], w1 = g_w[i + 1];
        uint4 u0 = ((const uint4*)(src + (size_t)g_dst[i] * 256))[lane];
        uint4 u1 = ((const uint4*)(src + (size_t)g_dst[i + 1] * 256))[lane];
        acc8(aA, u0, w0);
        acc8(aB, u1, w1);
    }
    if (i < e) {
        uint4 u0 = ((const uint4*)(src + (size_t)g_dst[i] * 256))[lane];
        acc8(aA, u0, g_w[i]);
    }
    float a[8];
#pragma unroll
    for (int j = 0; j < 8; j++) a[j] = aA[j] + aB[j];

    if (SUB >= 0) {
        const __half* sub = hbuf<(SUB >= 0 ? SUB : 1)>();
        uint4 su = ((const uint4*)(sub + (size_t)warp * 256))[lane];
        float sv[8];
        float2 f;
        f = __half22float2(*(__half2*)&su.x); sv[0] = f.x; sv[1] = f.y;
        f = __half22float2(*(__half2*)&su.y); sv[2] = f.x; sv[3] = f.y;
        f = __half22float2(*(__half2*)&su.z); sv[4] = f.x; sv[5] = f.y;
        f = __half22float2(*(__half2*)&su.w); sv[6] = f.x; sv[7] = f.y;
#pragma unroll
        for (int j = 0; j < 8; j++) a[j] = alpha * a[j] + beta * sv[j];
    }

    uint4 o;
    __half2 h;
    h = __floats2half2_rn(a[0], a[1]); o.x = *(uint32_t*)&h;
    h = __floats2half2_rn(a[2], a[3]); o.y = *(uint32_t*)&h;
    h = __floats2half2_rn(a[4], a[5]); o.z = *(uint32_t*)&h;
    h = __floats2half2_rn(a[6], a[7]); o.w = *(uint32_t*)&h;
    ((uint4*)(dst + (size_t)warp * 256))[lane] = o;
}

// ---------------- final SpMM: out(f32) += 2 * L @ P (P half, 128-wide) ----------------
__global__ __launch_bounds__(256)
void spmm_out_kernel(float* __restrict__ out) {
    int warp = (blockIdx.x * blockDim.x + threadIdx.x) >> 5;
    int lane = threadIdx.x & 31;
    if (warp >= N_NODES) return;
    int s = g_rowptr[warp];
    int e = g_rowptr[warp + 1];

    float aA[4] = {0, 0, 0, 0};
    float aB[4] = {0, 0, 0, 0};
    int i = s;
    for (; i + 2 <= e; i += 2) {
        float w0 = g_w[i], w1 = g_w[i + 1];
        uint2 u0 = ((const uint2*)(g_p + (size_t)g_dst[i] * 128))[lane];
        uint2 u1 = ((const uint2*)(g_p + (size_t)g_dst[i + 1] * 128))[lane];
        float2 f;
        f = __half22float2(*(__half2*)&u0.x); aA[0] += w0 * f.x; aA[1] += w0 * f.y;
        f = __half22float2(*(__half2*)&u0.y); aA[2] += w0 * f.x; aA[3] += w0 * f.y;
        f = __half22float2(*(__half2*)&u1.x); aB[0] += w1 * f.x; aB[1] += w1 * f.y;
        f = __half22float2(*(__half2*)&u1.y); aB[2] += w1 * f.x; aB[3] += w1 * f.y;
    }
    if (i < e) {
        float w0 = g_w[i];
        uint2 u0 = ((const uint2*)(g_p + (size_t)g_dst[i] * 128))[lane];
        float2 f;
        f = __half22float2(*(__half2*)&u0.x); aA[0] += w0 * f.x; aA[1] += w0 * f.y;
        f = __half22float2(*(__half2*)&u0.y); aA[2] += w0 * f.x; aA[3] += w0 * f.y;
    }
    float4* op = (float4*)(out + (size_t)warp * 128) + lane;
    float4 o = *op;
    o.x += 2.f * (aA[0] + aB[0]);
    o.y += 2.f * (aA[1] + aB[1]);
    o.z += 2.f * (aA[2] + aB[2]);
    o.w += 2.f * (aA[3] + aB[3]);
    *op = o;
}

// ---------------- fp16 mma GEMM, cp.async double-buffered ----------------
// Block 128(M) x 128(N), 256 threads, 8 warps (4m x 2n), warp tile 32x64,
// BK = 32 halfs, mma.m16n8k16. Static smem 40KB.
// LAYER 1: A=[x|tx1|tx2] (K=768), B=g_w1t, out=h (half, bias+relu).
// LAYER 2: A=[h|Z=tx1] (K=512), B=g_w2t, col<128 -> out(f32,+b2),
//          col>=128 -> P (half). P-half blocks (bn==128) skip stages 0-7
//          (their weights for k<256 are structurally zero).

template <int LAYER>
__global__ __launch_bounds__(256, 2)
void gemm_h(const float* __restrict__ bias, float* __restrict__ ext_out) {
    const int K  = (LAYER == 1) ? 768 : 512;
    const int NS = K / 32;

    __shared__ __align__(16) __half As[2][128][40];
    __shared__ __align__(16) __half Bs[2][128][40];

    const int tid  = threadIdx.x;
    const int lane = tid & 31;
    const int wid  = tid >> 5;
    const int g = lane >> 2;
    const int t = lane & 3;

    const int bm = blockIdx.y * 128;
    const int bn = blockIdx.x * 128;
    const int wm = (wid & 3) * 32;
    const int wn = (wid >> 2) * 64;

    // P-half of layer 2 depends only on Z (k >= 256): skip zero-weight stages.
    const int s0 = (LAYER == 2 && bn >= 128) ? 8 : 0;

    float acc[2][8][4];
#pragma unroll
    for (int i = 0; i < 2; i++)
#pragma unroll
        for (int j = 0; j < 8; j++)
#pragma unroll
            for (int q = 0; q < 4; q++) acc[i][j][q] = 0.f;

    auto issue = [&](int s) {
        const int buf = s & 1;
        const __half* seg;
        if (LAYER == 1) seg = (s < 8) ? g_x : ((s < 16) ? g_tx1 : g_tx2);
        else            seg = (s < 8) ? g_h : g_tx1;
        const __half* Bt = (LAYER == 1) ? g_w1t : g_w2t;
        const int kb = (s & 7) * 32;
#pragma unroll
        for (int p = 0; p < 2; p++) {
            int v = p * 256 + tid;
            int row = v >> 2, c = v & 3;
            int rg = bm + row;
            int ok = (rg < N_NODES) ? 16 : 0;
            const __half* src = seg + (size_t)(ok ? rg : 0) * 256 + kb + c * 8;
            cpasync16((uint32_t)__cvta_generic_to_shared(&As[buf][row][c * 8]), src, ok);
        }
#pragma unroll
        for (int p = 0; p < 2; p++) {
            int v = p * 256 + tid;
            int n = v >> 2, c = v & 3;
            const __half* src = Bt + (size_t)(bn + n) * K + s * 32 + c * 8;
            cpasync16((uint32_t)__cvta_generic_to_shared(&Bs[buf][n][c * 8]), src, 16);
        }
        cp_commit();
    };

    issue(s0);
    issue(s0 + 1);

    for (int s = s0; s < NS; s++) {
        if (s + 1 < NS) cp_wait1(); else cp_wait0();
        __syncthreads();
        const int buf = s & 1;
#pragma unroll
        for (int ks = 0; ks < 2; ks++) {
            const int k0 = ks * 16;
            uint32_t a[2][4];
            uint32_t b[8][2];
#pragma unroll
            for (int i = 0; i < 2; i++) {
                int r = wm + 16 * i + g;
                a[i][0] = *(const uint32_t*)&As[buf][r][k0 + 2 * t];
                a[i][1] = *(const uint32_t*)&As[buf][r + 8][k0 + 2 * t];
                a[i][2] = *(const uint32_t*)&As[buf][r][k0 + 2 * t + 8];
                a[i][3] = *(const uint32_t*)&As[buf][r + 8][k0 + 2 * t + 8];
            }
#pragma unroll
            for (int j = 0; j < 8; j++) {
                int n = wn + 8 * j + g;
                b[j][0] = *(const uint32_t*)&Bs[buf][n][k0 + 2 * t];
                b[j][1] = *(const uint32_t*)&Bs[buf][n][k0 + 2 * t + 8];
            }
#pragma unroll
            for (int i = 0; i < 2; i++)
#pragma unroll
                for (int j = 0; j < 8; j++)
                    mma_f16(acc[i][j], a[i], b[j]);
        }
        __syncthreads();
        if (s + 2 < NS) issue(s + 2);
    }

    // ---- epilogue ----
#pragma unroll
    for (int i = 0; i < 2; i++) {
        int r0 = bm + wm + 16 * i + g;
        int r1 = r0 + 8;
#pragma unroll
        for (int j = 0; j < 8; j++) {
            int col = bn + wn + 8 * j + 2 * t;
            float v0 = acc[i][j][0], v1 = acc[i][j][1];
            float v2 = acc[i][j][2], v3 = acc[i][j][3];
            if (LAYER == 1) {
                float bb0 = bias[col], bb1 = bias[col + 1];
                v0 = fmaxf(v0 + bb0, 0.f); v1 = fmaxf(v1 + bb1, 0.f);
                v2 = fmaxf(v2 + bb0, 0.f); v3 = fmaxf(v3 + bb1, 0.f);
                __half2 h01 = __floats2half2_rn(v0, v1);
                __half2 h23 = __floats2half2_rn(v2, v3);
                if (r0 < N_NODES) *(uint32_t*)(g_h + (size_t)r0 * 256 + col) = *(uint32_t*)&h01;
                if (r1 < N_NODES) *(uint32_t*)(g_h + (size_t)r1 * 256 + col) = *(uint32_t*)&h23;
            } else {
                if (col < 128) {
                    float bb0 = bias[col], bb1 = bias[col + 1];
                    if (r0 < N_NODES)
                        *(float2*)(ext_out + (size_t)r0 * 128 + col) = make_float2(v0 + bb0, v1 + bb1);
                    if (r1 < N_NODES)
                        *(float2*)(ext_out + (size_t)r1 * 128 + col) = make_float2(v2 + bb0, v3 + bb1);
                } else {
                    int pc = col - 128;
                    __half2 h01 = __floats2half2_rn(v0, v1);
                    __half2 h23 = __floats2half2_rn(v2, v3);
                    if (r0 < N_NODES) *(uint32_t*)(g_p + (size_t)r0 * 128 + pc) = *(uint32_t*)&h01;
                    if (r1 < N_NODES) *(uint32_t*)(g_p + (size_t)r1 * 128 + pc) = *(uint32_t*)&h23;
                }
            }
        }
    }
}

// ---------------- launch ----------------

extern "C" void kernel_launch(void* const* d_in, const int* in_sizes, int n_in,
                              void* d_out, int out_size) {
    const float* x  = (const float*)d_in[0];
    const int*   ei = (const int*)d_in[1];
    const float* ew = (const float*)d_in[2];
    const float* W1 = (const float*)d_in[3];   // [3,256,256]
    const float* b1 = (const float*)d_in[4];
    const float* W2 = (const float*)d_in[5];   // [3,256,128]
    const float* b2 = (const float*)d_in[6];
    float*       out = (float*)d_out;

    // CSR build + conversions (merged prelude: 6 launches)
    init_kernel<<<SCAN_BLOCKS, 256>>>(ei);
    prep_kernel<<<(N_NODES * 64 + 255) / 256, 256>>>(ei, ew, x, W1, W2);
    scan_pre_kernel<<<SCAN_BLOCKS, 256>>>();
    scan_mid_kernel<<<1, 256>>>();
    scan_post_kernel<<<SCAN_BLOCKS, 256>>>();
    build_kernel<<<(N_EDGES + 255) / 256, 256>>>(ei, ew);

    const int spmm_blocks = (N_NODES * 32 + 255) / 256;
    const dim3 ggrid(2, (N_NODES + 127) / 128);   // N=256 for both layers

    // ---- layer 1 ----
    spmm256_kernel<4, -1, 1><<<spmm_blocks, 256>>>(1.f, 0.f);   // tx1 = L @ x
    spmm256_kernel<1, 4, 2><<<spmm_blocks, 256>>>(2.f, -1.f);   // tx2 = 2 L tx1 - x
    gemm_h<1><<<ggrid, 256>>>(b1, nullptr);                     // h

    // ---- layer 2 (commuted + fused) ----
    spmm256_kernel<3, -1, 1><<<spmm_blocks, 256>>>(1.f, 0.f);   // Z = L @ h -> tx1
    gemm_h<2><<<ggrid, 256>>>(b2, out);                         // [out_partial | P]
    spmm_out_kernel<<<spmm_blocks, 256>>>(out);                 // out += 2 L P

    (void)in_sizes; (void)n_in; (void)out_size;
}